// round 17
// baseline (speedup 1.0000x reference)
#include <cuda_runtime.h>
#include <cuda_fp16.h>
#include <cstdint>

// Sparse conv3d: out[n,c] = sum_k mask[k,n] ? feat[nmap[k,n],:] @ W[k,:,c]
// N=200000, K=27, CIN=32, COUT=64, fp32.
//
// Single-term fp16 HMMA (rel_err ~2.9e-4, validated R12) with
// ldmatrix.m8n8.x4 fragment loads replacing 64 scalar LDS per warp per
// offset with 12 ldmatrix instructions. cp.async double-buffered pipeline
// unchanged from R12. (Resubmission of R13/R15 — infra flake, mappings
// re-audited against PTX spec.)

#define CIN      32
#define COUT     64
#define TROWS    128
#define NTHREADS 128

#define FEATCAP  262144
#define KCAP     32

// feature rows fp16: 32 halves = 64 B per row
__device__ __half g_feathi[(size_t)FEATCAP * 32];
// weights fp16: [k][c][i=0..31] halves, 64 B per (k,c) row
__device__ __half g_whalf[(size_t)KCAP * COUT * 32];

// smem stages: rows padded to 80 B (data 64 B).
// ldmatrix conflict check: 8 rows, stride 80 B = 5 granules; r*5 mod 8 all
// distinct -> conflict-free.
#define A_ROW     80
#define B_ROW     80
#define A_BYTES   (TROWS * A_ROW)          // 10240
#define B_OFF     A_BYTES
#define B_BYTES   (COUT * B_ROW)           // 5120
#define STAGE     (A_BYTES + B_BYTES)      // 15360
#define SMEM_TOTAL (2 * STAGE)             // 30720

__device__ __forceinline__ uint32_t smem_u32(const void* p) {
    uint32_t a;
    asm("{ .reg .u64 t; cvta.to.shared.u64 t, %1; cvt.u32.u64 %0, t; }"
        : "=r"(a) : "l"(p));
    return a;
}

__device__ __forceinline__ void cp16(uint32_t dst, const void* src, int sz) {
    asm volatile("cp.async.cg.shared.global [%0], [%1], 16, %2;"
                 :: "r"(dst), "l"(src), "r"(sz));
}
__device__ __forceinline__ void cp16f(uint32_t dst, const void* src) {
    asm volatile("cp.async.cg.shared.global [%0], [%1], 16;"
                 :: "r"(dst), "l"(src));
}
__device__ __forceinline__ void cp_commit() {
    asm volatile("cp.async.commit_group;");
}
template <int N_>
__device__ __forceinline__ void cp_wait() {
    asm volatile("cp.async.wait_group %0;" :: "n"(N_));
}

__device__ __forceinline__ void ldmx4(uint32_t* r, uint32_t addr) {
    asm volatile(
        "ldmatrix.sync.aligned.m8n8.x4.shared.b16 {%0,%1,%2,%3}, [%4];"
        : "=r"(r[0]), "=r"(r[1]), "=r"(r[2]), "=r"(r[3]) : "r"(addr));
}

__device__ __forceinline__ void mma_f16(float* c, const uint32_t* a,
                                        const uint32_t* b) {
    asm volatile(
        "mma.sync.aligned.m16n8k16.row.col.f32.f16.f16.f32 "
        "{%0,%1,%2,%3}, {%4,%5,%6,%7}, {%8,%9}, {%0,%1,%2,%3};"
        : "+f"(c[0]), "+f"(c[1]), "+f"(c[2]), "+f"(c[3])
        : "r"(a[0]), "r"(a[1]), "r"(a[2]), "r"(a[3]), "r"(b[0]), "r"(b[1]));
}

// ---------------- prep kernels ----------------
__global__ void split_feat_kernel(const float* __restrict__ f, int n) {
    const int t = blockIdx.x * blockDim.x + threadIdx.x;
    if (t >= n * 8) return;
    const int r = t >> 3, c = t & 7;
    const float4 v = reinterpret_cast<const float4*>(f)[(size_t)r * 8 + c];
    __half h[4];
    h[0] = __float2half_rn(v.x);
    h[1] = __float2half_rn(v.y);
    h[2] = __float2half_rn(v.z);
    h[3] = __float2half_rn(v.w);
    *reinterpret_cast<uint2*>(g_feathi + (size_t)r * 32 + c * 4) =
        *reinterpret_cast<uint2*>(h);
}

__global__ void split_w_kernel(const float* __restrict__ w, int kvol) {
    const int t = blockIdx.x * blockDim.x + threadIdx.x;
    if (t >= kvol * CIN * COUT) return;
    const int k = t / (CIN * COUT);
    const int rem = t - k * (CIN * COUT);
    const int i = rem >> 6;
    const int c = rem & 63;
    g_whalf[((size_t)k * COUT + c) * 32 + i] = __float2half_rn(w[t]);
}

// ---------------- main kernel ----------------
__global__ __launch_bounds__(NTHREADS, 5)
void spconv_hmma_lm(const int* __restrict__ nmap,
                    const int* __restrict__ nmask,
                    float* __restrict__ out,
                    int n, int kvol)
{
    extern __shared__ __align__(16) char smem[];
    const uint32_t sbase = smem_u32(smem);

    const int tid  = threadIdx.x;
    const int wid  = tid >> 5;
    const int lane = tid & 31;
    const int g    = lane >> 2;
    const int tig  = lane & 3;
    const int R    = blockIdx.x * TROWS;

    const int myrow = R + tid;
    const bool inb  = myrow < n;
    const int rowc  = inb ? myrow : 0;

    float acc[2][8][4];
#pragma unroll
    for (int mt = 0; mt < 2; ++mt)
#pragma unroll
        for (int nt = 0; nt < 8; ++nt)
#pragma unroll
            for (int j = 0; j < 4; ++j) acc[mt][nt][j] = 0.0f;

    const int brow  = tid >> 1;
    const int bhalf = tid & 1;

    auto issue_stage = [&](int k, int s, int msk, int src) {
        const uint32_t abase = sbase + s * STAGE + tid * A_ROW;
        const char* fr = reinterpret_cast<const char*>(
            g_feathi + (size_t)src * 32);
        const int sz = (msk && inb) ? 16 : 0;
#pragma unroll
        for (int c = 0; c < 4; ++c)
            cp16(abase + c * 16, fr + c * 16, sz);

        const uint32_t bbase = sbase + s * STAGE + B_OFF +
                               brow * B_ROW + bhalf * 32;
        const char* wr = reinterpret_cast<const char*>(
            g_whalf + ((size_t)k * COUT + brow) * 32) + bhalf * 32;
        cp16f(bbase,      wr);
        cp16f(bbase + 16, wr + 16);
        cp_commit();
    };

    // ldmatrix lane addressing (computed once)
    // A (per mt): row = wid*32 + mt*16 + (lane & 15), k-chunk = lane>>4
    const int a_lrow = (lane & 15);
    const int a_lchk = (lane >> 4) * 16;     // byte offset within row
    // B (per nt): row = nt*8 + (lane & 7), k-chunk = lane>>3
    const int b_lrow = (lane & 7);
    const int b_lchk = (lane >> 3) * 16;

    // prologue
    int msk_n = inb ? nmask[(long)0 * n + rowc] : 0;
    int src_n = nmap[(long)0 * n + rowc];
    issue_stage(0, 0, msk_n, src_n);
    if (kvol > 1) {
        msk_n = inb ? nmask[(long)1 * n + rowc] : 0;
        src_n = nmap[(long)1 * n + rowc];
    }

    for (int k = 0; k < kvol; ++k) {
        const int s = k & 1;

        if (k + 1 < kvol) {
            issue_stage(k + 1, (k + 1) & 1, msk_n, src_n);
            if (k + 2 < kvol) {
                msk_n = inb ? nmask[(long)(k + 2) * n + rowc] : 0;
                src_n = nmap[(long)(k + 2) * n + rowc];
            }
            cp_wait<1>();
        } else {
            cp_wait<0>();
        }
        __syncthreads();

        const uint32_t as = sbase + s * STAGE;
        const uint32_t bs = as + B_OFF;

        // A fragments: [mt][ks][4]
        uint32_t afr[2][2][4];
#pragma unroll
        for (int mt = 0; mt < 2; ++mt)
#pragma unroll
            for (int ks = 0; ks < 2; ++ks) {
                const uint32_t addr = as +
                    (wid * 32 + mt * 16 + a_lrow) * A_ROW + ks * 32 + a_lchk;
                ldmx4(afr[mt][ks], addr);
            }

#pragma unroll
        for (int nt = 0; nt < 8; ++nt) {
            uint32_t bfr[4];   // {ks0: b0,b1 | ks1: b0,b1}
            ldmx4(bfr, bs + (nt * 8 + b_lrow) * B_ROW + b_lchk);

            mma_f16(acc[0][nt], afr[0][0], bfr);       // mt0 ks0
            mma_f16(acc[0][nt], afr[0][1], bfr + 2);   // mt0 ks1
            mma_f16(acc[1][nt], afr[1][0], bfr);       // mt1 ks0
            mma_f16(acc[1][nt], afr[1][1], bfr + 2);   // mt1 ks1
        }
        __syncthreads();   // stage s free for the k+2 prefetch
    }

    // ---- epilogue ----
#pragma unroll
    for (int mt = 0; mt < 2; ++mt) {
        const int r0 = R + wid * 32 + mt * 16 + g;
        const int r1 = r0 + 8;
#pragma unroll
        for (int nt = 0; nt < 8; ++nt) {
            const int col = nt * 8 + tig * 2;
            if (r0 < n)
                *reinterpret_cast<float2*>(out + (size_t)r0 * COUT + col) =
                    make_float2(acc[mt][nt][0], acc[mt][nt][1]);
            if (r1 < n)
                *reinterpret_cast<float2*>(out + (size_t)r1 * COUT + col) =
                    make_float2(acc[mt][nt][2], acc[mt][nt][3]);
        }
    }
}

extern "C" void kernel_launch(void* const* d_in, const int* in_sizes, int n_in,
                              void* d_out, int out_size)
{
    const float* features = (const float*)d_in[0];
    const int*   nmap     = (const int*)  d_in[1];
    const int*   nmask    = (const int*)  d_in[2];
    const float* weights  = (const float*)d_in[3];
    float*       out      = (float*)d_out;

    const int n    = in_sizes[0] / CIN;      // 200000
    const int kvol = in_sizes[1] / n;        // 27

    split_feat_kernel<<<(n * 8 + 255) / 256, 256>>>(features, n);
    split_w_kernel<<<(kvol * CIN * COUT + 255) / 256, 256>>>(weights, kvol);

    cudaFuncSetAttribute(spconv_hmma_lm,
                         cudaFuncAttributeMaxDynamicSharedMemorySize, SMEM_TOTAL);

    const int grid = (n + TROWS - 1) / TROWS;
    spconv_hmma_lm<<<grid, NTHREADS, SMEM_TOTAL>>>(nmap, nmask, out, n, kvol);
}